// round 1
// baseline (speedup 1.0000x reference)
#include <cuda_runtime.h>
#include <cuda_bf16.h>
#include <cstdint>

#define Bsz 128
#define Tsz 400
#define Hsz 1024
#define Ssz 64
#define Csz 8
#define NEXC 819
#define NBLK 128

#define AN 0.2f            // DT/TAU_N
#define DTSEC 0.02f
#define NSTD 0.05f
#define AX_EVEN (20.0f/1500.0f)
#define AX_ODD  0.1f
#define U_EVEN  0.45f
#define U_ODD   0.15f

// ---------------- device scratch (allowed: __device__ globals) ----------------
__device__ float g_W[Hsz * Hsz];           // Dale's-law effective recurrent weights
__device__ float g_hp[2][Bsz * Hsz];       // ping-pong h_post
__device__ volatile unsigned int g_bar;    // grid barrier counter

// ---------------- init: build W_eff, reset barrier ----------------
__global__ void k_init(const float* __restrict__ w_rec) {
    int idx = blockIdx.x * blockDim.x + threadIdx.x;   // H*H threads exactly
    if (idx == 0) g_bar = 0;
    int i = idx >> 10;          // row (presynaptic)
    int j = idx & 1023;         // col
    float w = fmaxf(w_rec[idx], 0.0f);
    float s = (i < NEXC) ? 1.0f : -1.0f;
    g_W[idx] = (i == j) ? 0.0f : s * w;
}

// ---------------- persistent scan ----------------
__global__ void __launch_bounds__(256, 1) k_scan(
    const float* __restrict__ stim,   // [B,T,S]
    const float* __restrict__ ctx,    // [B,T,C]
    const float* __restrict__ b_rec,  // [1,H]
    const float* __restrict__ w_in,   // [H,S]
    const float* __restrict__ w_ctx,  // [H,C]
    const float* __restrict__ noise,  // [T,B,H]
    float* __restrict__ acts)         // [B,T,H]
{
    const int jt = blockIdx.x & 31;   // 32 column tiles
    const int mt = blockIdx.x >> 5;   // 4 row (batch) tiles
    const int j0 = jt * 32;
    const int m0 = mt * 32;
    const int tid  = threadIdx.x;
    const int lane = tid & 31;
    const int wrp  = tid >> 5;        // 8 warps
    const int nn   = lane;
    const int j    = j0 + nn;
    const int mmb  = wrp * 4;         // each warp owns 4 batch rows of the tile

    __shared__ float hpS[32 * 64];    // [mm][kk]
    __shared__ float wS [64 * 32];    // [kk][nn]
    __shared__ float W2s[72 * 32];    // [k][nn]  (w_in^T|w_ctx^T slice, resident)
    __shared__ float Xs [32 * 72];    // [mm][k]  (stim|ctx rows, per step)

    // resident feedforward weight slice for this block's 32 columns
    for (int q = tid; q < 72 * 32; q += 256) {
        int k = q >> 5, n2 = q & 31;
        int jj = j0 + n2;
        W2s[q] = (k < Ssz) ? w_in[jj * Ssz + k] : w_ctx[jj * Csz + (k - Ssz)];
    }

    const float brec = b_rec[j];
    const float ax = (j & 1) ? AX_ODD : AX_EVEN;
    const float Uj = (j & 1) ? U_ODD : U_EVEN;

    float h[4], sx[4], su[4];
#pragma unroll
    for (int r = 0; r < 4; r++) { h[r] = 0.0f; sx[r] = 1.0f; su[r] = Uj; }

    __syncthreads();

    for (int t = 0; t < Tsz; t++) {
        // ---- phase A: STP update, h_post, publish ----
        float* hpw = g_hp[t & 1];
#pragma unroll
        for (int r = 0; r < 4; r++) {
            float sx1 = sx[r] + ax * (1.0f - sx[r]) - DTSEC * su[r] * sx[r] * h[r];
            sx1 = fminf(fmaxf(sx1, 0.0f), 1.0f);
            float su1 = su[r] + ax * (Uj - su[r]) + DTSEC * Uj * (1.0f - su[r]) * h[r];
            su1 = fminf(fmaxf(su1, 0.0f), 1.0f);
            sx[r] = sx1; su[r] = su1;
            float hp = su1 * sx1 * h[r];
            hpw[(size_t)(m0 + mmb + r) * Hsz + j] = hp;
        }
        // stage stim/ctx rows for this step into Xs
        for (int q = tid; q < 32 * 16; q += 256) {
            int row = q >> 4, c4 = q & 15;
            const float4* sp = (const float4*)(stim + ((size_t)(m0 + row) * Tsz + t) * Ssz);
            *(float4*)(Xs + row * 72 + c4 * 4) = sp[c4];
        }
        for (int q = tid; q < 32 * 2; q += 256) {
            int row = q >> 1, c4 = q & 1;
            const float4* cp = (const float4*)(ctx + ((size_t)(m0 + row) * Tsz + t) * Csz);
            *(float4*)(Xs + row * 72 + 64 + c4 * 4) = cp[c4];
        }

        // ---- grid barrier (release->acquire) ----
        __threadfence();
        __syncthreads();
        if (tid == 0) {
            atomicAdd((unsigned int*)&g_bar, 1u);
            unsigned int target = (unsigned int)(t + 1) * NBLK;
            while (g_bar < target) { }
            __threadfence();
        }
        __syncthreads();

        // ---- phase B: dot over H (tiled) + drive over 72 ----
        float acc0 = 0.f, acc1 = 0.f, acc2 = 0.f, acc3 = 0.f;
        const float* hpr = g_hp[t & 1];
        for (int kt = 0; kt < 16; kt++) {
            const int k0 = kt * 64;
            for (int q = tid; q < 512; q += 256) {      // hp tile (bypass L1)
                int row = q >> 4, c4 = q & 15;
                float4 v = __ldcg((const float4*)(hpr + (size_t)(m0 + row) * Hsz + k0) + c4);
                *(float4*)(hpS + row * 64 + c4 * 4) = v;
            }
            for (int q = tid; q < 512; q += 256) {      // W tile
                int kk = q >> 3, c4 = q & 7;
                float4 v = *((const float4*)(g_W + (size_t)(k0 + kk) * Hsz + j0) + c4);
                *(float4*)(wS + kk * 32 + c4 * 4) = v;
            }
            __syncthreads();
#pragma unroll
            for (int g = 0; g < 16; g++) {
                float4 h0 = *(float4*)(hpS + (mmb + 0) * 64 + g * 4);
                float4 h1 = *(float4*)(hpS + (mmb + 1) * 64 + g * 4);
                float4 h2 = *(float4*)(hpS + (mmb + 2) * 64 + g * 4);
                float4 h3 = *(float4*)(hpS + (mmb + 3) * 64 + g * 4);
                float w0 = wS[(g * 4 + 0) * 32 + nn];
                float w1 = wS[(g * 4 + 1) * 32 + nn];
                float w2 = wS[(g * 4 + 2) * 32 + nn];
                float w3 = wS[(g * 4 + 3) * 32 + nn];
                acc0 += h0.x * w0 + h0.y * w1 + h0.z * w2 + h0.w * w3;
                acc1 += h1.x * w0 + h1.y * w1 + h1.z * w2 + h1.w * w3;
                acc2 += h2.x * w0 + h2.y * w1 + h2.z * w2 + h2.w * w3;
                acc3 += h3.x * w0 + h3.y * w1 + h3.z * w2 + h3.w * w3;
            }
            __syncthreads();
        }
        // drive: 72-wide extension
#pragma unroll
        for (int g = 0; g < 18; g++) {
            float4 x0 = *(float4*)(Xs + (mmb + 0) * 72 + g * 4);
            float4 x1 = *(float4*)(Xs + (mmb + 1) * 72 + g * 4);
            float4 x2 = *(float4*)(Xs + (mmb + 2) * 72 + g * 4);
            float4 x3 = *(float4*)(Xs + (mmb + 3) * 72 + g * 4);
            float w0 = W2s[(g * 4 + 0) * 32 + nn];
            float w1 = W2s[(g * 4 + 1) * 32 + nn];
            float w2 = W2s[(g * 4 + 2) * 32 + nn];
            float w3 = W2s[(g * 4 + 3) * 32 + nn];
            acc0 += x0.x * w0 + x0.y * w1 + x0.z * w2 + x0.w * w3;
            acc1 += x1.x * w0 + x1.y * w1 + x1.z * w2 + x1.w * w3;
            acc2 += x2.x * w0 + x2.y * w1 + x2.z * w2 + x2.w * w3;
            acc3 += x3.x * w0 + x3.y * w1 + x3.z * w2 + x3.w * w3;
        }

        // ---- h update + acts write ----
        float accs[4] = {acc0, acc1, acc2, acc3};
#pragma unroll
        for (int r = 0; r < 4; r++) {
            int b = m0 + mmb + r;
            float nz = noise[((size_t)t * Bsz + b) * Hsz + j];
            float hn = h[r] * (1.0f - AN) + AN * (accs[r] + brec) + NSTD * nz;
            hn = fmaxf(hn, 0.0f);
            h[r] = hn;
            acts[((size_t)b * Tsz + t) * Hsz + j] = hn;
        }
        __syncthreads();   // protect Xs against next step's restaging
    }
}

// ---------------- epilogue: output + classifier heads ----------------
__global__ void k_heads(
    const float* __restrict__ acts,   // [B,T,H]
    const float* __restrict__ w_out,  // [3,H]
    const float* __restrict__ b_out,  // [3]
    const float* __restrict__ c1_w,   // [3,2,H]
    const float* __restrict__ c1_b,   // [3,2]
    const float* __restrict__ c2_w,   // [3,8,2]
    const float* __restrict__ c2_b,   // [3,8]
    float* __restrict__ outputs,      // [B,T,3]
    float* __restrict__ p)            // [B,T,3,8]
{
    int gw = (blockIdx.x * blockDim.x + threadIdx.x) >> 5;
    int lane = threadIdx.x & 31;
    if (gw >= Bsz * Tsz) return;

    const float4* a4 = (const float4*)(acts + (size_t)gw * Hsz);
    const float4* v0 = (const float4*)(w_out);
    const float4* v1 = (const float4*)(w_out + Hsz);
    const float4* v2 = (const float4*)(w_out + 2 * Hsz);
    const float4* v3 = (const float4*)(c1_w);
    const float4* v4 = (const float4*)(c1_w + Hsz);
    const float4* v5 = (const float4*)(c1_w + 2 * Hsz);
    const float4* v6 = (const float4*)(c1_w + 3 * Hsz);
    const float4* v7 = (const float4*)(c1_w + 4 * Hsz);
    const float4* v8 = (const float4*)(c1_w + 5 * Hsz);

    float s0=0,s1=0,s2=0,s3=0,s4=0,s5=0,s6=0,s7=0,s8=0;
    for (int c = lane; c < Hsz / 4; c += 32) {
        float4 a = a4[c];
        float4 w;
        w = v0[c]; s0 += a.x*w.x + a.y*w.y + a.z*w.z + a.w*w.w;
        w = v1[c]; s1 += a.x*w.x + a.y*w.y + a.z*w.z + a.w*w.w;
        w = v2[c]; s2 += a.x*w.x + a.y*w.y + a.z*w.z + a.w*w.w;
        w = v3[c]; s3 += a.x*w.x + a.y*w.y + a.z*w.z + a.w*w.w;
        w = v4[c]; s4 += a.x*w.x + a.y*w.y + a.z*w.z + a.w*w.w;
        w = v5[c]; s5 += a.x*w.x + a.y*w.y + a.z*w.z + a.w*w.w;
        w = v6[c]; s6 += a.x*w.x + a.y*w.y + a.z*w.z + a.w*w.w;
        w = v7[c]; s7 += a.x*w.x + a.y*w.y + a.z*w.z + a.w*w.w;
        w = v8[c]; s8 += a.x*w.x + a.y*w.y + a.z*w.z + a.w*w.w;
    }
#pragma unroll
    for (int off = 16; off > 0; off >>= 1) {
        s0 += __shfl_xor_sync(0xffffffffu, s0, off);
        s1 += __shfl_xor_sync(0xffffffffu, s1, off);
        s2 += __shfl_xor_sync(0xffffffffu, s2, off);
        s3 += __shfl_xor_sync(0xffffffffu, s3, off);
        s4 += __shfl_xor_sync(0xffffffffu, s4, off);
        s5 += __shfl_xor_sync(0xffffffffu, s5, off);
        s6 += __shfl_xor_sync(0xffffffffu, s6, off);
        s7 += __shfl_xor_sync(0xffffffffu, s7, off);
        s8 += __shfl_xor_sync(0xffffffffu, s8, off);
    }
    if (lane == 0) {
        outputs[(size_t)gw * 3 + 0] = s0 + b_out[0];
        outputs[(size_t)gw * 3 + 1] = s1 + b_out[1];
        outputs[(size_t)gw * 3 + 2] = s2 + b_out[2];
        float z[6] = { s3 + c1_b[0], s4 + c1_b[1], s5 + c1_b[2],
                       s6 + c1_b[3], s7 + c1_b[4], s8 + c1_b[5] };
#pragma unroll
        for (int jj = 0; jj < 3; jj++)
#pragma unroll
            for (int o = 0; o < 8; o++) {
                float val = z[jj*2+0] * c2_w[(jj*8+o)*2 + 0]
                          + z[jj*2+1] * c2_w[(jj*8+o)*2 + 1]
                          + c2_b[jj*8 + o];
                p[(size_t)gw * 24 + jj * 8 + o] = val;
            }
    }
}

// ---------------- launch ----------------
extern "C" void kernel_launch(void* const* d_in, const int* in_sizes, int n_in,
                              void* d_out, int out_size) {
    const float* stim  = (const float*)d_in[0];
    const float* ctx   = (const float*)d_in[1];
    const float* w_rec = (const float*)d_in[2];
    const float* b_rec = (const float*)d_in[3];
    const float* w_in  = (const float*)d_in[4];
    const float* w_ctx = (const float*)d_in[5];
    const float* w_out = (const float*)d_in[6];
    const float* b_out = (const float*)d_in[7];
    const float* c1_w  = (const float*)d_in[8];
    const float* c1_b  = (const float*)d_in[9];
    const float* c2_w  = (const float*)d_in[10];
    const float* c2_b  = (const float*)d_in[11];
    const float* noise = (const float*)d_in[12];

    float* out     = (float*)d_out;
    float* outputs = out;                                   // [B,T,3]
    float* acts    = out + (size_t)Bsz * Tsz * 3;           // [B,T,H]
    float* p       = acts + (size_t)Bsz * Tsz * Hsz;        // [B,T,3,8]

    k_init <<<(Hsz * Hsz) / 256, 256>>>(w_rec);
    k_scan <<<NBLK, 256>>>(stim, ctx, b_rec, w_in, w_ctx, noise, acts);
    k_heads<<<(Bsz * Tsz) / 8, 256>>>(acts, w_out, b_out, c1_w, c1_b, c2_w, c2_b,
                                      outputs, p);
}

// round 3
// speedup vs baseline: 1.4955x; 1.4955x over previous
#include <cuda_runtime.h>
#include <cstdint>

#define Bsz 128
#define Tsz 400
#define Hsz 1024
#define Ssz 64
#define Csz 8
#define NEXC 819
#define NBLK 128

#define AN 0.2f            // DT/TAU_N
#define DTSEC 0.02f
#define NSTD 0.05f
#define AX_EVEN (20.0f/1500.0f)
#define AX_ODD  0.1f
#define U_EVEN  0.45f
#define U_ODD   0.15f

#define HP_STR 132         // 128 duplicated floats + 4 pad (16B-aligned rows)
#define RED_WSTR 1056      // 32 rows * 33 floats per warp partial block

typedef unsigned long long u64;

// ---------------- device scratch ----------------
__device__ float g_W[Hsz * Hsz];           // Dale's-law effective recurrent weights
__device__ float g_hp[2][Bsz * Hsz];       // ping-pong h_post
__device__ volatile unsigned int g_bar;    // grid barrier counter

__device__ __forceinline__ void fma2(u64 &d, u64 a, u64 b) {
    asm("fma.rn.f32x2 %0, %1, %2, %0;" : "+l"(d) : "l"(a), "l"(b));
}
__device__ __forceinline__ float2 u2f2(u64 u) {
    float2 f;
    asm("mov.b64 {%0, %1}, %2;" : "=f"(f.x), "=f"(f.y) : "l"(u));
    return f;
}

// ---------------- init: build W_eff, reset barrier ----------------
__global__ void k_init(const float* __restrict__ w_rec) {
    int idx = blockIdx.x * blockDim.x + threadIdx.x;   // H*H threads exactly
    if (idx == 0) g_bar = 0;
    int i = idx >> 10;          // row (presynaptic)
    int j = idx & 1023;         // col
    float w = fmaxf(w_rec[idx], 0.0f);
    float s = (i < NEXC) ? 1.0f : -1.0f;
    g_W[idx] = (i == j) ? 0.0f : s * w;
}

// ---------------- persistent scan ----------------
__global__ void __launch_bounds__(256, 1) k_scan(
    const float* __restrict__ stim,   // [B,T,S]
    const float* __restrict__ ctx,    // [B,T,C]
    const float* __restrict__ b_rec,  // [1,H]
    const float* __restrict__ w_in,   // [H,S]
    const float* __restrict__ w_ctx,  // [H,C]
    const float* __restrict__ noise,  // [T,B,H]
    float* __restrict__ acts)         // [B,T,H]
{
    extern __shared__ float sm[];
    float* hpS  = sm;            // [32][HP_STR]  h_post, k-duplicated pairs
    float* W2s  = sm + 4224;     // [72][32]      (w_in^T|w_ctx^T slice, resident)
    float* Xs   = sm + 6528;     // [32][72]      (stim|ctx rows, per step)
    float* redS = sm + 8832;     // [8][RED_WSTR] split-K partials

    const int jt = blockIdx.x & 31;   // 32 column tiles
    const int mt = blockIdx.x >> 5;   // 4 batch tiles
    const int j0 = jt * 32;
    const int m0 = mt * 32;
    const int tid  = threadIdx.x;
    const int lane = tid & 31;
    const int wrp  = tid >> 5;        // 8 warps: each owns a K-slice
    const int g    = lane >> 3;       // m-group 0..3  (lane's rows: m = 4r+g)
    const int e    = lane & 7;        // n-group 0..7  (lane's cols: n = 4e..4e+3)
    const int j    = j0 + lane;       // phase-A / update column
    const int mmb  = wrp * 4;         // phase-A rows

    // resident feedforward weight slice for this block's 32 columns
    for (int q = tid; q < 72 * 32; q += 256) {
        int k = q >> 5, n2 = q & 31;
        int jj = j0 + n2;
        W2s[q] = (k < Ssz) ? w_in[jj * Ssz + k] : w_ctx[jj * Csz + (k - Ssz)];
    }

    const float brec = b_rec[j];
    const float ax = (j & 1) ? AX_ODD : AX_EVEN;
    const float Uj = (j & 1) ? U_ODD : U_EVEN;

    float h[4], sx[4], su[4];
#pragma unroll
    for (int r = 0; r < 4; r++) { h[r] = 0.0f; sx[r] = 1.0f; su[r] = Uj; }

    __syncthreads();

    for (int t = 0; t < Tsz; t++) {
        // ---- phase A: STP update, h_post, publish ----
        float* hpw = g_hp[t & 1];
#pragma unroll
        for (int r = 0; r < 4; r++) {
            float sx1 = sx[r] + ax * (1.0f - sx[r]) - DTSEC * su[r] * sx[r] * h[r];
            sx1 = fminf(fmaxf(sx1, 0.0f), 1.0f);
            float su1 = su[r] + ax * (Uj - su[r]) + DTSEC * Uj * (1.0f - su[r]) * h[r];
            su1 = fminf(fmaxf(su1, 0.0f), 1.0f);
            sx[r] = sx1; su[r] = su1;
            float hp = su1 * sx1 * h[r];
            hpw[(size_t)(m0 + mmb + r) * Hsz + j] = hp;
        }
        // stage stim/ctx rows for this step into Xs
        for (int q = tid; q < 32 * 16; q += 256) {
            int row = q >> 4, c4 = q & 15;
            const float4* sp = (const float4*)(stim + ((size_t)(m0 + row) * Tsz + t) * Ssz);
            *(float4*)(Xs + row * 72 + c4 * 4) = sp[c4];
        }
        for (int q = tid; q < 32 * 2; q += 256) {
            int row = q >> 1, c4 = q & 1;
            const float4* cp = (const float4*)(ctx + ((size_t)(m0 + row) * Tsz + t) * Csz);
            *(float4*)(Xs + row * 72 + 64 + c4 * 4) = cp[c4];
        }

        // ---- grid barrier (release->acquire) ----
        __threadfence();
        __syncthreads();
        if (tid == 0) {
            atomicAdd((unsigned int*)&g_bar, 1u);
            unsigned int target = (unsigned int)(t + 1) * NBLK;
            while (g_bar < target) { }
            __threadfence();
        }
        __syncthreads();

        // ---- phase B: split-K f32x2 GEMM ----
        u64 acc[8][2];
#pragma unroll
        for (int r = 0; r < 8; r++) { acc[r][0] = 0ull; acc[r][1] = 0ull; }

        const float* hpr = g_hp[t & 1];
        for (int kt = 0; kt < 16; kt++) {
            const int k0 = kt * 64;
            // stage h_post chunk, duplicating each value (f32x2 broadcast operand).
            // Interleaved (row,cs) mapping keeps each 8-lane STS.128 phase conflict-free.
            for (int q = tid; q < 512; q += 256) {
                int row = (q & 1) + ((q >> 5) << 1);
                int cs  = (q >> 1) & 15;
                float4 v = __ldcg((const float4*)(hpr + (size_t)(m0 + row) * Hsz + k0) + cs);
                float* d = hpS + row * HP_STR + cs * 8;
                *(float4*)(d)     = make_float4(v.x, v.x, v.y, v.y);
                *(float4*)(d + 4) = make_float4(v.z, v.z, v.w, v.w);
            }
            __syncthreads();

            // warp wrp owns k in [k0 + wrp*8, k0 + wrp*8 + 8)
            const float* wb = g_W + (size_t)(k0 + wrp * 8) * Hsz + j0 + 4 * e;
            const float* hb = hpS + g * HP_STR + 16 * wrp;   // + 2*k_local
#pragma unroll
            for (int kk = 0; kk < 8; kk++) {
                u64 w0 = *(const u64*)(wb + kk * Hsz);       // W[k][n], W[k][n+1]
                u64 w1 = *(const u64*)(wb + kk * Hsz + 2);   // W[k][n+2], W[k][n+3]
#pragma unroll
                for (int r = 0; r < 8; r++) {
                    u64 hh = *(const u64*)(hb + r * (4 * HP_STR) + 2 * kk); // (hp,hp)
                    fma2(acc[r][0], hh, w0);
                    fma2(acc[r][1], hh, w1);
                }
            }
            __syncthreads();
        }

        // ---- write split-K partials (conflict-free: 33-float row stride) ----
        {
            float* rw = redS + wrp * RED_WSTR + g * 33 + 4 * e;
#pragma unroll
            for (int r = 0; r < 8; r++) {
                float2 v0 = u2f2(acc[r][0]);
                float2 v1 = u2f2(acc[r][1]);
                float* p = rw + r * (4 * 33);
                p[0] = v0.x; p[1] = v0.y; p[2] = v1.x; p[3] = v1.y;
            }
        }
        __syncthreads();

        // ---- reduce 8 warps + drive + h update (phase-A mapping) ----
        float accs[4];
#pragma unroll
        for (int r = 0; r < 4; r++) {
            int m = mmb + r;
            float s = 0.0f;
#pragma unroll
            for (int w = 0; w < 8; w++) s += redS[w * RED_WSTR + m * 33 + lane];
            accs[r] = s;
        }

        // drive: 72-wide extension
#pragma unroll
        for (int g2 = 0; g2 < 18; g2++) {
            float w0 = W2s[(g2 * 4 + 0) * 32 + lane];
            float w1 = W2s[(g2 * 4 + 1) * 32 + lane];
            float w2 = W2s[(g2 * 4 + 2) * 32 + lane];
            float w3 = W2s[(g2 * 4 + 3) * 32 + lane];
#pragma unroll
            for (int r = 0; r < 4; r++) {
                float4 x = *(float4*)(Xs + (mmb + r) * 72 + g2 * 4);
                accs[r] += x.x * w0 + x.y * w1 + x.z * w2 + x.w * w3;
            }
        }

#pragma unroll
        for (int r = 0; r < 4; r++) {
            int b = m0 + mmb + r;
            float nz = noise[((size_t)t * Bsz + b) * Hsz + j];
            float hn = h[r] * (1.0f - AN) + AN * (accs[r] + brec) + NSTD * nz;
            hn = fmaxf(hn, 0.0f);
            h[r] = hn;
            acts[((size_t)b * Tsz + t) * Hsz + j] = hn;
        }
        __syncthreads();   // protect Xs/redS against next step's reuse
    }
}

// ---------------- epilogue: output + classifier heads ----------------
__global__ void k_heads(
    const float* __restrict__ acts,   // [B,T,H]
    const float* __restrict__ w_out,  // [3,H]
    const float* __restrict__ b_out,  // [3]
    const float* __restrict__ c1_w,   // [3,2,H]
    const float* __restrict__ c1_b,   // [3,2]
    const float* __restrict__ c2_w,   // [3,8,2]
    const float* __restrict__ c2_b,   // [3,8]
    float* __restrict__ outputs,      // [B,T,3]
    float* __restrict__ p)            // [B,T,3,8]
{
    int gw = (blockIdx.x * blockDim.x + threadIdx.x) >> 5;
    int lane = threadIdx.x & 31;
    if (gw >= Bsz * Tsz) return;

    const float4* a4 = (const float4*)(acts + (size_t)gw * Hsz);
    const float4* v0 = (const float4*)(w_out);
    const float4* v1 = (const float4*)(w_out + Hsz);
    const float4* v2 = (const float4*)(w_out + 2 * Hsz);
    const float4* v3 = (const float4*)(c1_w);
    const float4* v4 = (const float4*)(c1_w + Hsz);
    const float4* v5 = (const float4*)(c1_w + 2 * Hsz);
    const float4* v6 = (const float4*)(c1_w + 3 * Hsz);
    const float4* v7 = (const float4*)(c1_w + 4 * Hsz);
    const float4* v8 = (const float4*)(c1_w + 5 * Hsz);

    float s0=0,s1=0,s2=0,s3=0,s4=0,s5=0,s6=0,s7=0,s8=0;
    for (int c = lane; c < Hsz / 4; c += 32) {
        float4 a = a4[c];
        float4 w;
        w = v0[c]; s0 += a.x*w.x + a.y*w.y + a.z*w.z + a.w*w.w;
        w = v1[c]; s1 += a.x*w.x + a.y*w.y + a.z*w.z + a.w*w.w;
        w = v2[c]; s2 += a.x*w.x + a.y*w.y + a.z*w.z + a.w*w.w;
        w = v3[c]; s3 += a.x*w.x + a.y*w.y + a.z*w.z + a.w*w.w;
        w = v4[c]; s4 += a.x*w.x + a.y*w.y + a.z*w.z + a.w*w.w;
        w = v5[c]; s5 += a.x*w.x + a.y*w.y + a.z*w.z + a.w*w.w;
        w = v6[c]; s6 += a.x*w.x + a.y*w.y + a.z*w.z + a.w*w.w;
        w = v7[c]; s7 += a.x*w.x + a.y*w.y + a.z*w.z + a.w*w.w;
        w = v8[c]; s8 += a.x*w.x + a.y*w.y + a.z*w.z + a.w*w.w;
    }
#pragma unroll
    for (int off = 16; off > 0; off >>= 1) {
        s0 += __shfl_xor_sync(0xffffffffu, s0, off);
        s1 += __shfl_xor_sync(0xffffffffu, s1, off);
        s2 += __shfl_xor_sync(0xffffffffu, s2, off);
        s3 += __shfl_xor_sync(0xffffffffu, s3, off);
        s4 += __shfl_xor_sync(0xffffffffu, s4, off);
        s5 += __shfl_xor_sync(0xffffffffu, s5, off);
        s6 += __shfl_xor_sync(0xffffffffu, s6, off);
        s7 += __shfl_xor_sync(0xffffffffu, s7, off);
        s8 += __shfl_xor_sync(0xffffffffu, s8, off);
    }
    if (lane == 0) {
        outputs[(size_t)gw * 3 + 0] = s0 + b_out[0];
        outputs[(size_t)gw * 3 + 1] = s1 + b_out[1];
        outputs[(size_t)gw * 3 + 2] = s2 + b_out[2];
        float z[6] = { s3 + c1_b[0], s4 + c1_b[1], s5 + c1_b[2],
                       s6 + c1_b[3], s7 + c1_b[4], s8 + c1_b[5] };
#pragma unroll
        for (int jj = 0; jj < 3; jj++)
#pragma unroll
            for (int o = 0; o < 8; o++) {
                float val = z[jj*2+0] * c2_w[(jj*8+o)*2 + 0]
                          + z[jj*2+1] * c2_w[(jj*8+o)*2 + 1]
                          + c2_b[jj*8 + o];
                p[(size_t)gw * 24 + jj * 8 + o] = val;
            }
    }
}

// ---------------- launch ----------------
extern "C" void kernel_launch(void* const* d_in, const int* in_sizes, int n_in,
                              void* d_out, int out_size) {
    const float* stim  = (const float*)d_in[0];
    const float* ctx   = (const float*)d_in[1];
    const float* w_rec = (const float*)d_in[2];
    const float* b_rec = (const float*)d_in[3];
    const float* w_in  = (const float*)d_in[4];
    const float* w_ctx = (const float*)d_in[5];
    const float* w_out = (const float*)d_in[6];
    const float* b_out = (const float*)d_in[7];
    const float* c1_w  = (const float*)d_in[8];
    const float* c1_b  = (const float*)d_in[9];
    const float* c2_w  = (const float*)d_in[10];
    const float* c2_b  = (const float*)d_in[11];
    const float* noise = (const float*)d_in[12];

    float* out     = (float*)d_out;
    float* outputs = out;                                   // [B,T,3]
    float* acts    = out + (size_t)Bsz * Tsz * 3;           // [B,T,H]
    float* p       = acts + (size_t)Bsz * Tsz * Hsz;        // [B,T,3,8]

    const int smem_bytes = (8832 + 8 * RED_WSTR) * 4;       // 69120 B
    cudaFuncSetAttribute(k_scan, cudaFuncAttributeMaxDynamicSharedMemorySize, smem_bytes);

    k_init <<<(Hsz * Hsz) / 256, 256>>>(w_rec);
    k_scan <<<NBLK, 256, smem_bytes>>>(stim, ctx, b_rec, w_in, w_ctx, noise, acts);
    k_heads<<<(Bsz * Tsz) / 8, 256>>>(acts, w_out, b_out, c1_w, c1_b, c2_w, c2_b,
                                      outputs, p);
}